// round 1
// baseline (speedup 1.0000x reference)
#include <cuda_runtime.h>

#define NB   256   // threads per block == rows per block
#define NBLK 256   // 256*256 = 65536 rows exactly
#define ALPHA 0.01f

// ---- shared memory layout (float offsets) ----
#define S_WIN   0        // 3 * 8*64 = 1536
#define S_BIN   1536     // 3 * 64   = 192
#define S_WA1   1728     // 64
#define S_WA2   1792     // 64
#define S_WO1   1856     // 10*32 = 320
#define S_BO1   2176     // 32
#define S_WO2   2208     // 32*16 = 512
#define S_BO2   2720     // 16
#define S_WO3   2736     // 16
#define S_BO3   2752     // 1
#define S_WFC1  2753     // 90*64 = 5760
#define S_BFC1  8513     // 64
#define S_WIH   8577     // 192*64 = 12288
#define S_BIH   20865    // 192
#define S_WHH   21057    // 192*64 = 12288
#define S_BHH   33345    // 192
#define S_WFC2  33537    // 64*5 = 320
#define S_BFC2  33857    // 5
#define S_OBS   33862    // 256*85 = 21760 (later reused as per-row scratch, stride 65)
#define S_TOT   (33862 + 21760)   // 55622 floats = 222488 bytes

__device__ __forceinline__ float lrelu(float v) { return fmaxf(v, ALPHA * v); }

__global__ void __launch_bounds__(NB, 1)
atom_rnn_kernel(const float* __restrict__ g_obs, const float* __restrict__ g_hid,
                const float* __restrict__ w_in0, const float* __restrict__ b_in0,
                const float* __restrict__ w_in1, const float* __restrict__ b_in1,
                const float* __restrict__ w_in2, const float* __restrict__ b_in2,
                const float* __restrict__ g_W,  const float* __restrict__ g_a,
                const float* __restrict__ w_o1, const float* __restrict__ b_o1,
                const float* __restrict__ w_o2, const float* __restrict__ b_o2,
                const float* __restrict__ w_o3, const float* __restrict__ b_o3,
                const float* __restrict__ w_fc1, const float* __restrict__ b_fc1,
                const float* __restrict__ w_ih, const float* __restrict__ w_hh,
                const float* __restrict__ b_ih, const float* __restrict__ b_hh,
                const float* __restrict__ w_fc2, const float* __restrict__ b_fc2,
                float* __restrict__ out_q, float* __restrict__ out_h)
{
    extern __shared__ float sm[];
    const int tid = threadIdx.x;

    // ---------------- stage weights into shared ----------------
    #define CPY(off, src, n) for (int i = tid; i < (n); i += NB) sm[(off) + i] = (src)[i]
    CPY(S_WIN,        w_in0, 512);
    CPY(S_WIN + 512,  w_in1, 512);
    CPY(S_WIN + 1024, w_in2, 512);
    CPY(S_BIN,        b_in0, 64);
    CPY(S_BIN + 64,   b_in1, 64);
    CPY(S_BIN + 128,  b_in2, 64);
    CPY(S_WO1, w_o1, 320);  CPY(S_BO1, b_o1, 32);
    CPY(S_WO2, w_o2, 512);  CPY(S_BO2, b_o2, 16);
    CPY(S_WO3, w_o3, 16);   CPY(S_BO3, b_o3, 1);
    CPY(S_WFC1, w_fc1, 5760); CPY(S_BFC1, b_fc1, 64);
    CPY(S_WIH, w_ih, 12288);  CPY(S_BIH, b_ih, 192);
    CPY(S_WHH, w_hh, 12288);  CPY(S_BHH, b_hh, 192);
    CPY(S_WFC2, w_fc2, 320);  CPY(S_BFC2, b_fc2, 5);
    #undef CPY

    // Wa1 = W @ a[:64], Wa2 = W @ a[64:]  (folds the 64x64 GEMM out of the hot path)
    if (tid < 128) {
        const int j = tid & 63;
        const float* av = g_a + ((tid < 64) ? 0 : 64);
        const float* wr = g_W + j * 64;
        float s = 0.f;
        #pragma unroll 8
        for (int m = 0; m < 64; ++m) s = fmaf(wr[m], av[m], s);
        sm[((tid < 64) ? S_WA1 : S_WA2) + j] = s;
    }

    // stage this block's obs tile (coalesced)
    {
        const size_t base = (size_t)blockIdx.x * NB * 85;
        for (int i = tid; i < NB * 85; i += NB) sm[S_OBS + i] = g_obs[base + i];
    }
    __syncthreads();

    const int row = blockIdx.x * NB + tid;
    const float* orow = &sm[S_OBS + tid * 85];   // stride 85: coprime w/ 32 banks -> conflict-free

    // ---------------- stage 1: tokens -> wh1/wh2 ----------------
    float wh1[10], wh2[10];
    #pragma unroll
    for (int t = 0; t < 10; ++t) {
        float o[8];
        #pragma unroll
        for (int f = 0; f < 8; ++f) o[f] = orow[(t * 8 + f + 4) % 80];
        const int sel = (t < 5) ? 0 : ((t < 9) ? 1 : 2);
        const float* w   = &sm[S_WIN + sel * 512];
        const float* b   = &sm[S_BIN + sel * 64];
        const float* wa1 = &sm[S_WA1];
        const float* wa2 = &sm[S_WA2];
        float s1 = 0.f, s2 = 0.f;
        #pragma unroll 4
        for (int j = 0; j < 64; ++j) {
            float hm = b[j];
            #pragma unroll
            for (int f = 0; f < 8; ++f) hm = fmaf(o[f], w[f * 64 + j], hm);
            hm = lrelu(hm);
            s1 = fmaf(hm, wa1[j], s1);
            s2 = fmaf(hm, wa2[j], s2);
        }
        wh1[t] = s1; wh2[t] = s2;
    }

    // ---------------- stage 2: attention + output head ----------------
    // att1 path: ex[c][r] = exp(e[5+c][r]-m_c), den[c] = 1/sum
    float ex[5][5], den[5];
    #pragma unroll
    for (int c = 0; c < 5; ++c) {
        float ev[5]; float mx = -1e30f;
        #pragma unroll
        for (int r2 = 0; r2 < 5; ++r2) {
            float v = lrelu(wh1[5 + c] + wh2[r2]);
            ev[r2] = v; mx = fmaxf(mx, v);
        }
        float d = 0.f;
        #pragma unroll
        for (int r2 = 0; r2 < 5; ++r2) { float e_ = __expf(ev[r2] - mx); ex[c][r2] = e_; d += e_; }
        den[c] = 1.0f / d;
    }

    float hpv[5];
    #pragma unroll
    for (int r = 0; r < 5; ++r) {
        float att[10];
        {
            float ev[5]; float mx = -1e30f;
            #pragma unroll
            for (int c = 0; c < 5; ++c) {
                float v = lrelu(wh1[r] + wh2[5 + c]);
                ev[c] = v; mx = fmaxf(mx, v);
            }
            float d = 0.f;
            #pragma unroll
            for (int c = 0; c < 5; ++c) { float e_ = __expf(ev[c] - mx); att[c] = e_; d += e_; }
            float inv = 1.0f / d;
            #pragma unroll
            for (int c = 0; c < 5; ++c) att[c] *= inv;
            #pragma unroll
            for (int c = 0; c < 5; ++c) att[5 + c] = ex[c][r] * den[c];
        }
        float h1[32];
        #pragma unroll
        for (int j = 0; j < 32; ++j) {
            float v = sm[S_BO1 + j];
            #pragma unroll
            for (int k = 0; k < 10; ++k) v = fmaf(att[k], sm[S_WO1 + k * 32 + j], v);
            h1[j] = lrelu(v);
        }
        float h2v[16];
        #pragma unroll
        for (int j = 0; j < 16; ++j) {
            float v = sm[S_BO2 + j];
            #pragma unroll
            for (int k = 0; k < 32; ++k) v = fmaf(h1[k], sm[S_WO2 + k * 16 + j], v);
            h2v[j] = lrelu(v);
        }
        float v = sm[S_BO3];
        #pragma unroll
        for (int k = 0; k < 16; ++k) v = fmaf(h2v[k], sm[S_WO3 + k], v);
        hpv[r] = lrelu(v);
    }

    float obs_out[5];
    {
        float mx = hpv[0];
        #pragma unroll
        for (int r = 1; r < 5; ++r) mx = fmaxf(mx, hpv[r]);
        float d = 0.f;
        #pragma unroll
        for (int r = 0; r < 5; ++r) { obs_out[r] = __expf(hpv[r] - mx); d += obs_out[r]; }
        float inv = 1.0f / d;
        #pragma unroll
        for (int r = 0; r < 5; ++r) obs_out[r] *= inv;
    }

    // ---------------- stage 3: fc1 ----------------
    float x[64];
    #pragma unroll
    for (int j = 0; j < 64; ++j) x[j] = sm[S_BFC1 + j];
    #pragma unroll 1
    for (int k = 0; k < 85; ++k) {
        const float ok = orow[k];
        const float* wr = &sm[S_WFC1 + k * 64];
        #pragma unroll
        for (int j = 0; j < 64; ++j) x[j] = fmaf(ok, wr[j], x[j]);
    }
    #pragma unroll
    for (int m = 0; m < 5; ++m) {
        const float om = obs_out[m];
        const float* wr = &sm[S_WFC1 + (85 + m) * 64];
        #pragma unroll
        for (int j = 0; j < 64; ++j) x[j] = fmaf(om, wr[j], x[j]);
    }
    #pragma unroll
    for (int j = 0; j < 64; ++j) x[j] = fmaxf(x[j], 0.f);

    // ---------------- stage 4: GRU + q ----------------
    float hi[64];
    {
        const float4* hp4 = reinterpret_cast<const float4*>(g_hid + (size_t)row * 64);
        #pragma unroll
        for (int i = 0; i < 16; ++i) {
            float4 v = hp4[i];
            hi[4*i] = v.x; hi[4*i+1] = v.y; hi[4*i+2] = v.z; hi[4*i+3] = v.w;
        }
    }
    __syncthreads();                     // obs tile dead -> reuse as per-row scratch
    float* scr = &sm[S_OBS + tid * 65];  // stride 65 -> conflict-free dynamic access
    #pragma unroll
    for (int k = 0; k < 64; ++k) scr[k] = hi[k];

    float hq[5];
    #pragma unroll
    for (int m = 0; m < 5; ++m) hq[m] = sm[S_BFC2 + m];

    #pragma unroll 1
    for (int j = 0; j < 64; ++j) {
        const float* wi_r = &sm[S_WIH + j * 64];
        const float* wi_z = &sm[S_WIH + (64 + j) * 64];
        const float* wi_n = &sm[S_WIH + (128 + j) * 64];
        const float* wh_r = &sm[S_WHH + j * 64];
        const float* wh_z = &sm[S_WHH + (64 + j) * 64];
        const float* wh_n = &sm[S_WHH + (128 + j) * 64];
        float ar  = sm[S_BIH + j]      + sm[S_BHH + j];
        float az  = sm[S_BIH + 64 + j] + sm[S_BHH + 64 + j];
        float ani = sm[S_BIH + 128 + j];
        float anh = sm[S_BHH + 128 + j];
        #pragma unroll
        for (int k = 0; k < 64; ++k) {
            ar  = fmaf(x[k],  wi_r[k], ar);
            ar  = fmaf(hi[k], wh_r[k], ar);
            az  = fmaf(x[k],  wi_z[k], az);
            az  = fmaf(hi[k], wh_z[k], az);
            ani = fmaf(x[k],  wi_n[k], ani);
            anh = fmaf(hi[k], wh_n[k], anh);
        }
        const float r_ = 1.0f / (1.0f + __expf(-ar));
        const float z_ = 1.0f / (1.0f + __expf(-az));
        const float n_ = tanhf(fmaf(r_, anh, ani));
        const float hj = scr[j];                    // h_in[j]
        const float h_ = n_ + z_ * (hj - n_);       // (1-z)n + z*h_in
        scr[j] = h_;
        #pragma unroll
        for (int m = 0; m < 5; ++m) hq[m] = fmaf(h_, sm[S_WFC2 + j * 5 + m], hq[m]);
    }

    // ---------------- stores ----------------
    {
        float* qp = out_q + (size_t)row * 5;
        #pragma unroll
        for (int m = 0; m < 5; ++m) qp[m] = hq[m];

        float4* ho4 = reinterpret_cast<float4*>(out_h + (size_t)row * 64);
        #pragma unroll 1
        for (int i = 0; i < 16; ++i) {
            float4 v;
            v.x = scr[4*i]; v.y = scr[4*i+1]; v.z = scr[4*i+2]; v.w = scr[4*i+3];
            ho4[i] = v;
        }
    }
}

extern "C" void kernel_launch(void* const* d_in, const int* in_sizes, int n_in,
                              void* d_out, int out_size)
{
    const float* g_obs  = (const float*)d_in[0];
    const float* g_hid  = (const float*)d_in[1];
    const float* w_in0  = (const float*)d_in[2];
    const float* b_in0  = (const float*)d_in[3];
    const float* w_in1  = (const float*)d_in[4];
    const float* b_in1  = (const float*)d_in[5];
    const float* w_in2  = (const float*)d_in[6];
    const float* b_in2  = (const float*)d_in[7];
    const float* g_W    = (const float*)d_in[8];
    const float* g_a    = (const float*)d_in[9];
    const float* w_o1   = (const float*)d_in[10];
    const float* b_o1   = (const float*)d_in[11];
    const float* w_o2   = (const float*)d_in[12];
    const float* b_o2   = (const float*)d_in[13];
    const float* w_o3   = (const float*)d_in[14];
    const float* b_o3   = (const float*)d_in[15];
    const float* w_fc1  = (const float*)d_in[16];
    const float* b_fc1  = (const float*)d_in[17];
    const float* w_ih   = (const float*)d_in[18];
    const float* w_hh   = (const float*)d_in[19];
    const float* b_ih   = (const float*)d_in[20];
    const float* b_hh   = (const float*)d_in[21];
    const float* w_fc2  = (const float*)d_in[22];
    const float* b_fc2  = (const float*)d_in[23];

    float* out   = (float*)d_out;
    float* out_q = out;                          // q: (65536, 5) flattened first
    float* out_h = out + (size_t)65536 * 5;      // h: (65536, 64) after

    const int smem_bytes = S_TOT * 4;            // 222488 B
    cudaFuncSetAttribute(atom_rnn_kernel,
                         cudaFuncAttributeMaxDynamicSharedMemorySize, smem_bytes);

    atom_rnn_kernel<<<NBLK, NB, smem_bytes>>>(
        g_obs, g_hid, w_in0, b_in0, w_in1, b_in1, w_in2, b_in2, g_W, g_a,
        w_o1, b_o1, w_o2, b_o2, w_o3, b_o3, w_fc1, b_fc1,
        w_ih, w_hh, b_ih, b_hh, w_fc2, b_fc2, out_q, out_h);
}